// round 13
// baseline (speedup 1.0000x reference)
#include <cuda_runtime.h>
#include <cuda_bf16.h>
#include <cstdint>

#define RAYS 16384
#define NCS 64
#define NFS 128
#define NTS 192

#define WPB 10                       // warps per block
#define BLK (WPB * 32)
#define HROW 160                     // weight row pitch (bytes); conflict-free lds64

__device__ float g_w[RAYS * NCS];                 // coarse weights
__device__ float g_z[RAYS * NTS];                 // merged z_vals
__device__ float4 g_rgbd[RAYS * (NCS + NTS)];     // per-point {r,g,b,density}

// ===========================================================================
// helpers
// ===========================================================================
__device__ __forceinline__ uint32_t smem_u32(const void* p) {
    uint32_t a;
    asm("{ .reg .u64 t; cvta.to.shared.u64 t, %1; cvt.u32.u64 %0, t; }" : "=r"(a) : "l"(p));
    return a;
}
__device__ __forceinline__ void lds64(uint32_t a, uint32_t& x, uint32_t& y) {
    asm volatile("ld.shared.v2.b32 {%0, %1}, [%2];" : "=r"(x), "=r"(y) : "r"(a));
}
__device__ __forceinline__ void mma16816(float* c, const uint32_t* a, uint32_t b0, uint32_t b1) {
    asm volatile(
        "mma.sync.aligned.m16n8k16.row.col.f32.bf16.bf16.f32 "
        "{%0, %1, %2, %3}, {%4, %5, %6, %7}, {%8, %9}, {%0, %1, %2, %3};"
        : "+f"(c[0]), "+f"(c[1]), "+f"(c[2]), "+f"(c[3])
        : "r"(a[0]), "r"(a[1]), "r"(a[2]), "r"(a[3]), "r"(b0), "r"(b1));
}
__device__ __forceinline__ uint32_t bf16x2_rn(float f0, float f1) {
    uint32_t r;
    asm("cvt.rn.bf16x2.f32 %0, %1, %2;" : "=r"(r) : "f"(f1), "f"(f0));
    return r;
}
__device__ __forceinline__ void split2(float f0, float f1, uint32_t& hi, uint32_t& lo) {
    hi = bf16x2_rn(f0, f1);
    const float r0 = __uint_as_float(hi << 16);
    const float r1 = __uint_as_float(hi & 0xffff0000u);
    lo = bf16x2_rn(f0 - r0, f1 - r1);
}
// permuted B-weight byte offset within a row (lane's two fragment regs adjacent)
__device__ __forceinline__ uint32_t bperm_off(int k) {
    const int kt = k >> 4, r = k & 15;
    return (uint32_t)(kt * 32 + ((r & 7) >> 1) * 8 + (r >> 3) * 4 + (r & 1) * 2);
}

// ===========================================================================
// Batched MLP via mma.sync bf16 (split-3, fp32 accum).
// 320 threads = 10 warps, 2 blocks/SM; each warp owns 16 points per iter
// (MT=1: C shrinks to 32 regs -> ~100 regs -> 20 warps/SM).
// Layer1 computed DIRECTLY in A-fragment layout; biases folded into C init.
// mode 0: coarse (t from near/far); mode 1: fine (t from g_z).
// ===========================================================================
__global__ void __launch_bounds__(BLK, 2) mlp_kernel(
    int mode, int wtotal,
    const float* __restrict__ origins, const float* __restrict__ dirs,
    const float* __restrict__ nearp, const float* __restrict__ farp,
    const float* __restrict__ W1, const float* __restrict__ B1,
    const float* __restrict__ W2, const float* __restrict__ B2,
    const float* __restrict__ WR, const float* __restrict__ BR,
    const float* __restrict__ WD, const float* __restrict__ BD,
    float4* __restrict__ outp)
{
    __shared__ __align__(16) char sW2H[64 * HROW];   // W2^T [n][perm k] bf16
    __shared__ __align__(16) char sW2L[64 * HROW];
    __shared__ __align__(16) char sW3H[8 * HROW];    // [rgb,d,0..0][perm k]
    __shared__ __align__(16) char sW3L[8 * HROW];
    __shared__ __align__(16) float4 sW14[64];        // {w1x, w1y, w1z, b1}
    __shared__ __align__(16) float sB2[64];
    __shared__ __align__(16) float sBR8[8];          // {br0,br1,br2,bd,0,0,0,0}
    __shared__ __align__(16) float sOut[WPB][16][4];

    const int tid = threadIdx.x;
    const int warp = tid >> 5;
    const int lane = tid & 31;

    // ---- stage weights (permuted k layout) ----
    for (int e = tid; e < 4096; e += BLK) {
        const int n = e >> 6, k = e & 63;
        const float w = W2[k * 64 + n];
        const __nv_bfloat16 hb = __float2bfloat16(w);
        const uint32_t off = (uint32_t)n * HROW + bperm_off(k);
        *(__nv_bfloat16*)(sW2H + off) = hb;
        *(__nv_bfloat16*)(sW2L + off) = __float2bfloat16(w - __bfloat162float(hb));
    }
    for (int e = tid; e < 512; e += BLK) {
        const int n = e >> 6, k = e & 63;
        const float w = (n < 3) ? WR[k * 3 + n] : ((n == 3) ? WD[k] : 0.0f);
        const __nv_bfloat16 hb = __float2bfloat16(w);
        const uint32_t off = (uint32_t)n * HROW + bperm_off(k);
        *(__nv_bfloat16*)(sW3H + off) = hb;
        *(__nv_bfloat16*)(sW3L + off) = __float2bfloat16(w - __bfloat162float(hb));
    }
    for (int e = tid; e < 64; e += BLK) {
        sW14[e] = make_float4(W1[e], W1[64 + e], W1[128 + e], B1[e]);
        sB2[e] = B2[e];
    }
    if (tid < 8) sBR8[tid] = (tid < 3) ? BR[tid] : ((tid == 3) ? BD[0] : 0.0f);
    __syncthreads();

    const uint32_t w2hB = smem_u32(sW2H);
    const uint32_t w2lB = smem_u32(sW2L);
    const uint32_t w3hB = smem_u32(sW3H);
    const uint32_t w3lB = smem_u32(sW3L);
    const uint32_t b2B  = smem_u32(sB2);
    const uint32_t br8B = smem_u32(sBR8);

    const int g = lane >> 2;
    const int j0 = (lane & 3) * 2;
    const uint32_t bOff = (uint32_t)g * HROW + (uint32_t)(lane & 3) * 8;

    for (int wt = blockIdx.x * WPB + warp; wt < wtotal; wt += gridDim.x * WPB) {
        // ---- ray + per-lane t values (tile = 16 points, within one ray) ----
        const int ray = (mode == 0) ? (wt >> 2) : (wt / 12);
        const float ox = origins[3 * ray + 0], oy = origins[3 * ray + 1], oz = origins[3 * ray + 2];
        const float dx = dirs[3 * ray + 0], dy = dirs[3 * ray + 1], dz = dirs[3 * ray + 2];
        float tv[2];
        if (mode == 0) {
            const float nb = nearp[ray], fb = farp[ray];
            const int base = (wt & 3) * 16;
#pragma unroll
            for (int a = 0; a < 2; ++a) {
                const float u = (float)(base + 8 * a + g) * (1.0f / 63.0f);
                tv[a] = nb * (1.0f - u) + fb * u;
            }
        } else {
#pragma unroll
            for (int a = 0; a < 2; ++a)
                tv[a] = g_z[wt * 16 + 8 * a + g];
        }

        float pX[2], pY[2], pZ[2];
#pragma unroll
        for (int a = 0; a < 2; ++a) {
            pX[a] = fmaf(tv[a], dx, ox);
            pY[a] = fmaf(tv[a], dy, oy);
            pZ[a] = fmaf(tv[a], dz, oz);
        }

        // ---- C init = b2 bias ----
        float C[8][4];
#pragma unroll
        for (int nt = 0; nt < 8; ++nt) {
            uint32_t bx, by;
            lds64(b2B + (uint32_t)(nt * 8 + j0) * 4, bx, by);
            C[nt][0] = __uint_as_float(bx); C[nt][1] = __uint_as_float(by);
            C[nt][2] = C[nt][0]; C[nt][3] = C[nt][1];
        }

        // ---- layer1 fragment-direct + layer2 MMA ----
#pragma unroll
        for (int kt = 0; kt < 4; ++kt) {
            const int c0 = kt * 16 + j0;
            const float4 wa = sW14[c0], wb = sW14[c0 + 1];
            const float4 wc = sW14[c0 + 8], wd = sW14[c0 + 9];

            uint32_t Ah[4], Al[4];
            {
                const float v00 = fmaxf(fmaf(pX[0], wa.x, fmaf(pY[0], wa.y, fmaf(pZ[0], wa.z, wa.w))), 0.0f);
                const float v01 = fmaxf(fmaf(pX[0], wb.x, fmaf(pY[0], wb.y, fmaf(pZ[0], wb.z, wb.w))), 0.0f);
                const float v02 = fmaxf(fmaf(pX[0], wc.x, fmaf(pY[0], wc.y, fmaf(pZ[0], wc.z, wc.w))), 0.0f);
                const float v03 = fmaxf(fmaf(pX[0], wd.x, fmaf(pY[0], wd.y, fmaf(pZ[0], wd.z, wd.w))), 0.0f);
                const float v10 = fmaxf(fmaf(pX[1], wa.x, fmaf(pY[1], wa.y, fmaf(pZ[1], wa.z, wa.w))), 0.0f);
                const float v11 = fmaxf(fmaf(pX[1], wb.x, fmaf(pY[1], wb.y, fmaf(pZ[1], wb.z, wb.w))), 0.0f);
                const float v12 = fmaxf(fmaf(pX[1], wc.x, fmaf(pY[1], wc.y, fmaf(pZ[1], wc.z, wc.w))), 0.0f);
                const float v13 = fmaxf(fmaf(pX[1], wd.x, fmaf(pY[1], wd.y, fmaf(pZ[1], wd.z, wd.w))), 0.0f);
                split2(v00, v01, Ah[0], Al[0]);
                split2(v10, v11, Ah[1], Al[1]);
                split2(v02, v03, Ah[2], Al[2]);
                split2(v12, v13, Ah[3], Al[3]);
            }
#pragma unroll
            for (int hf = 0; hf < 2; ++hf) {
                uint32_t bh[4][2], bl[4][2];
#pragma unroll
                for (int n4 = 0; n4 < 4; ++n4) {
                    const uint32_t ba = (uint32_t)(hf * 4 + n4) * (8 * HROW) + bOff + kt * 32;
                    lds64(w2hB + ba, bh[n4][0], bh[n4][1]);
                    lds64(w2lB + ba, bl[n4][0], bl[n4][1]);
                }
#pragma unroll
                for (int n4 = 0; n4 < 4; ++n4) {
                    float* Cp = C[hf * 4 + n4];
                    mma16816(Cp, Ah, bh[n4][0], bh[n4][1]);
                    mma16816(Cp, Ah, bl[n4][0], bl[n4][1]);
                    mma16816(Cp, Al, bh[n4][0], bh[n4][1]);
                }
            }
        }

        // ---- C3 init = output bias ----
        float C3[4];
        {
            uint32_t bx, by;
            lds64(br8B + (uint32_t)j0 * 4, bx, by);
            C3[0] = __uint_as_float(bx); C3[1] = __uint_as_float(by);
            C3[2] = C3[0]; C3[3] = C3[1];
        }

        // ---- layer3: A3 repacked straight from C regs ----
#pragma unroll
        for (int kt = 0; kt < 4; ++kt) {
            const int nt0 = 2 * kt, nt1 = 2 * kt + 1;
            uint32_t b3h0, b3h1, b3l0, b3l1;
            lds64(w3hB + bOff + kt * 32, b3h0, b3h1);
            lds64(w3lB + bOff + kt * 32, b3l0, b3l1);
            const float v00 = fmaxf(C[nt0][0], 0.0f);
            const float v01 = fmaxf(C[nt0][1], 0.0f);
            const float v02 = fmaxf(C[nt0][2], 0.0f);
            const float v03 = fmaxf(C[nt0][3], 0.0f);
            const float v10 = fmaxf(C[nt1][0], 0.0f);
            const float v11 = fmaxf(C[nt1][1], 0.0f);
            const float v12 = fmaxf(C[nt1][2], 0.0f);
            const float v13 = fmaxf(C[nt1][3], 0.0f);
            uint32_t A3h[4], A3l[4];
            split2(v00, v01, A3h[0], A3l[0]);
            split2(v02, v03, A3h[1], A3l[1]);
            split2(v10, v11, A3h[2], A3l[2]);
            split2(v12, v13, A3h[3], A3l[3]);
            mma16816(C3, A3h, b3h0, b3h1);
            mma16816(C3, A3h, b3l0, b3l1);
            mma16816(C3, A3l, b3h0, b3h1);
        }

        // ---- transpose via sOut, activate, store ----
        if ((lane & 3) < 2) {
            *(float2*)&sOut[warp][g][j0] = make_float2(C3[0], C3[1]);
            *(float2*)&sOut[warp][g + 8][j0] = make_float2(C3[2], C3[3]);
        }
        __syncwarp();
        if (lane < 16) {
            const float4 o4 = *(const float4*)&sOut[warp][lane][0];
            outp[wt * 16 + lane] = make_float4(1.0f / (1.0f + __expf(-o4.x)),
                                              1.0f / (1.0f + __expf(-o4.y)),
                                              1.0f / (1.0f + __expf(-o4.z)),
                                              fmaxf(o4.w, 0.0f));
        }
        __syncwarp();
    }
}

// ===========================================================================
// Coarse render: warp/ray, 2 samples/lane.  (VERBATIM from R10 pass)
// ===========================================================================
__global__ void __launch_bounds__(256) coarse_render(
    const float* __restrict__ origins, const float* __restrict__ dirs,
    const float* __restrict__ nearp, const float* __restrict__ farp,
    const float* __restrict__ bkgd, float* __restrict__ out)
{
    const int lane = threadIdx.x & 31;
    const int ray = blockIdx.x * 8 + (threadIdx.x >> 5);
    const int i0 = 2 * lane, i1 = 2 * lane + 1;

    const float nb = nearp[ray], fb = farp[ray];
    const float ti0 = (float)i0 * (1.0f / 63.0f);
    const float ti1 = (float)i1 * (1.0f / 63.0f);
    const float ti2 = (float)(i1 + 1) * (1.0f / 63.0f);
    const float t0 = nb * (1.0f - ti0) + fb * ti0;
    const float t1 = nb * (1.0f - ti1) + fb * ti1;
    const float t2 = nb * (1.0f - ti2) + fb * ti2;

    const float dx = dirs[3 * ray + 0], dy = dirs[3 * ray + 1], dz = dirs[3 * ray + 2];
    const float dn = sqrtf(dx * dx + dy * dy + dz * dz);

    const float4 q0 = g_rgbd[ray * NCS + i0];
    const float4 q1 = g_rgbd[ray * NCS + i1];
    const float dd0 = q0.w * (t1 - t0) * dn;
    const float dd1 = q1.w * ((i1 == 63) ? 1e10f : (t2 - t1)) * dn;

    float s = dd0 + dd1;
#pragma unroll
    for (int off = 1; off < 32; off <<= 1) {
        float n = __shfl_up_sync(0xffffffffu, s, off);
        if (lane >= off) s += n;
    }
    const float prev = __shfl_up_sync(0xffffffffu, s, 1);
    const float excl = (lane == 0) ? 0.0f : prev;

    const float w0 = (1.0f - __expf(-dd0)) * __expf(-excl);
    const float w1 = (1.0f - __expf(-dd1)) * __expf(-(excl + dd0));
    {
        unsigned long long pk;
        asm("mov.b64 %0, {%1, %2};" : "=l"(pk) : "f"(w0), "f"(w1));
        reinterpret_cast<unsigned long long*>(g_w)[ray * 32 + lane] = pk;
    }

    const float n0 = nearp[0], f0 = farp[0];
    const float t00 = n0 * (1.0f - ti0) + f0 * ti0;
    const float t01 = n0 * (1.0f - ti1) + f0 * ti1;

    float v[6] = { fmaf(w0, q0.x, w1 * q1.x), fmaf(w0, q0.y, w1 * q1.y),
                   fmaf(w0, q0.z, w1 * q1.z), w0 + w1,
                   fmaf(w0, t0, w1 * t1), fmaf(w0, t00, w1 * t01) };
#pragma unroll
    for (int q = 0; q < 6; ++q) {
#pragma unroll
        for (int off = 16; off >= 1; off >>= 1)
            v[q] += __shfl_xor_sync(0xffffffffu, v[q], off);
    }
    if (lane == 0) {
        const float acc = v[3], om = 1.0f - acc;
        float* o = out + (size_t)ray * 16;
        o[0] = v[0] + bkgd[0] * om;
        o[1] = v[1] + bkgd[1] * om;
        o[2] = v[2] + bkgd[2] * om;
        o[3] = v[4];
        o[4] = acc;
        o[5] = fmaf(v[5], dirs[0], acc * origins[0]);
        o[6] = fmaf(v[5], dirs[1], acc * origins[1]);
        o[7] = fmaf(v[5], dirs[2], acc * origins[2]);
    }
}

// ===========================================================================
// Parallel inverse-CDF + rank-merge: warp per ray.  (VERBATIM from R10 pass)
// ===========================================================================
#define TVAL(idx) (nb * (1.0f - (float)(idx) * (1.0f/63.0f)) + fb * ((float)(idx) * (1.0f/63.0f)))
#define BINV(idx) (0.5f * (TVAL(idx) + TVAL((idx)+1)))

__global__ void __launch_bounds__(256) sample_kernel(
    const float* __restrict__ nearp, const float* __restrict__ farp)
{
    __shared__ float scdf[8][64];
    __shared__ float szs[8][128];
    const int warp = threadIdx.x >> 5;
    const int lane = threadIdx.x & 31;
    const int ray = blockIdx.x * 8 + warp;
    const float nb = nearp[ray], fb = farp[ray];
    const float* gw = g_w + ray * NCS;

    const float wA = gw[1 + lane];
    const float wB = (lane < 30) ? gw[33 + lane] : 0.0f;
    float tsum = wA + wB;
#pragma unroll
    for (int off = 16; off >= 1; off >>= 1)
        tsum += __shfl_xor_sync(0xffffffffu, tsum, off);
    const float pad = fmaxf(1e-5f - tsum, 0.0f);
    const float padd = pad * (1.0f / 62.0f);
    const float inv = 1.0f / (tsum + pad);
    const float pA = (wA + padd) * inv;
    const float pB = (wB + padd) * inv;

    float s1 = pA, s2 = pB;
#pragma unroll
    for (int off = 1; off < 32; off <<= 1) {
        float n1 = __shfl_up_sync(0xffffffffu, s1, off);
        float n2 = __shfl_up_sync(0xffffffffu, s2, off);
        if (lane >= off) { s1 += n1; s2 += n2; }
    }
    const float T1 = __shfl_sync(0xffffffffu, s1, 31);
    if (lane == 0) scdf[warp][0] = 0.0f;
    scdf[warp][1 + lane] = fminf(s1, 1.0f);
    if (lane < 29) scdf[warp][33 + lane] = fminf(T1 + s2, 1.0f);
    if (lane == 31) scdf[warp][62] = 1.0f;
    __syncwarp();

    const float* cdf = scdf[warp];
    const float du = (1.0f - 1.1920929e-7f) * (1.0f / 127.0f);
    float zloc[4];
#pragma unroll
    for (int s = 0; s < 4; ++s) {
        const int sidx = lane * 4 + s;
        const float u = (float)sidx * du;
        int k = 0;
#pragma unroll
        for (int st = 32; st >= 1; st >>= 1)
            if (k + st <= 61 && cdf[k + st] <= u) k += st;
        const float c0 = cdf[k], c1 = cdf[k + 1];
        float tt = (u - c0) / (c1 - c0);
        tt = fminf(fmaxf(tt, 0.0f), 1.0f);
        const float b0 = BINV(k), b1 = BINV(k + 1);
        zloc[s] = b0 + tt * (b1 - b0);
        szs[warp][sidx] = zloc[s];
    }
    __syncwarp();

    float* zout = g_z + (size_t)ray * NTS;
#pragma unroll
    for (int s = 0; s < 4; ++s) {
        const int sidx = lane * 4 + s;
        const float z = zloc[s];
        int i0 = (int)floorf((z - nb) / (fb - nb) * 63.0f);
        i0 = max(-1, min(63, i0));
        while (i0 + 1 <= 63 && TVAL(i0 + 1) <= z) ++i0;
        while (i0 >= 0 && TVAL(i0) > z) --i0;
        zout[sidx + i0 + 1] = z;
    }
#pragma unroll
    for (int r = 0; r < 2; ++r) {
        const int i = lane * 2 + r;
        const float tvv = TVAL(i);
        int c = 0;
#pragma unroll
        for (int st = 128; st >= 1; st >>= 1)
            if (c + st <= 128 && szs[warp][c + st - 1] < tvv) c += st;
        zout[i + c] = tvv;
    }
}
#undef TVAL
#undef BINV

// ===========================================================================
// Fine render: warp/ray, 6 samples/lane.  (VERBATIM from R10 pass)
// ===========================================================================
__global__ void __launch_bounds__(256) fine_render(
    const float* __restrict__ origins, const float* __restrict__ dirs,
    const float* __restrict__ bkgd, float* __restrict__ out)
{
    const int lane = threadIdx.x & 31;
    const int ray = blockIdx.x * 8 + (threadIdx.x >> 5);
    const float4* sc = g_rgbd + RAYS * NCS + (size_t)ray * NTS;
    const float* zr = g_z + (size_t)ray * NTS;
    const int j0 = lane * 6;

    const float dx = dirs[3 * ray + 0], dy = dirs[3 * ray + 1], dz = dirs[3 * ray + 2];
    const float dn = sqrtf(dx * dx + dy * dy + dz * dz);

    float z[7];
#pragma unroll
    for (int s = 0; s < 6; ++s) z[s] = zr[j0 + s];
    z[6] = (lane == 31) ? 0.0f : zr[j0 + 6];

    float dd[6], pre[6];
    float running = 0.0f;
#pragma unroll
    for (int s = 0; s < 6; ++s) {
        const float td = (lane == 31 && s == 5) ? 1e10f : (z[s + 1] - z[s]);
        dd[s] = sc[j0 + s].w * td * dn;
        running += dd[s];
        pre[s] = running;
    }

    float ssum = pre[5];
#pragma unroll
    for (int off = 1; off < 32; off <<= 1) {
        float n = __shfl_up_sync(0xffffffffu, ssum, off);
        if (lane >= off) ssum += n;
    }
    const float prev = __shfl_up_sync(0xffffffffu, ssum, 1);
    const float base = (lane == 0) ? 0.0f : prev;

    float v[6] = {0.0f, 0.0f, 0.0f, 0.0f, 0.0f, 0.0f};
#pragma unroll
    for (int s = 0; s < 6; ++s) {
        const float excl = base + ((s == 0) ? 0.0f : pre[s - 1]);
        const float w = (1.0f - __expf(-dd[s])) * __expf(-excl);
        const float4 q = sc[j0 + s];
        v[0] = fmaf(w, q.x, v[0]);
        v[1] = fmaf(w, q.y, v[1]);
        v[2] = fmaf(w, q.z, v[2]);
        v[3] += w;
        v[4] = fmaf(w, z[s], v[4]);
        v[5] = fmaf(w, g_z[j0 + s], v[5]);   // ray-0 z (pts1 quirk)
    }
#pragma unroll
    for (int q = 0; q < 6; ++q) {
#pragma unroll
        for (int off = 16; off >= 1; off >>= 1)
            v[q] += __shfl_xor_sync(0xffffffffu, v[q], off);
    }
    if (lane == 0) {
        const float acc = v[3], om = 1.0f - acc;
        float* o = out + (size_t)ray * 16;
        o[8]  = v[0] + bkgd[0] * om;
        o[9]  = v[1] + bkgd[1] * om;
        o[10] = v[2] + bkgd[2] * om;
        o[11] = v[4];
        o[12] = acc;
        o[13] = fmaf(v[5], dirs[0], acc * origins[0]);
        o[14] = fmaf(v[5], dirs[1], acc * origins[1]);
        o[15] = fmaf(v[5], dirs[2], acc * origins[2]);
    }
}

// ===========================================================================
extern "C" void kernel_launch(void* const* d_in, const int* in_sizes, int n_in,
                              void* d_out, int out_size)
{
    (void)in_sizes; (void)n_in; (void)out_size;
    const float* origins = (const float*)d_in[0];
    const float* dirs    = (const float*)d_in[1];
    const float* nearp   = (const float*)d_in[2];
    const float* farp    = (const float*)d_in[3];
    const float* bkgd    = (const float*)d_in[4];
    const float* w1c = (const float*)d_in[5];
    const float* b1c = (const float*)d_in[6];
    const float* w2c = (const float*)d_in[7];
    const float* b2c = (const float*)d_in[8];
    const float* wrc = (const float*)d_in[9];
    const float* brc = (const float*)d_in[10];
    const float* wdc = (const float*)d_in[11];
    const float* bdc = (const float*)d_in[12];
    const float* w1f = (const float*)d_in[13];
    const float* b1f = (const float*)d_in[14];
    const float* w2f = (const float*)d_in[15];
    const float* b2f = (const float*)d_in[16];
    const float* wrf = (const float*)d_in[17];
    const float* brf = (const float*)d_in[18];
    const float* wdf = (const float*)d_in[19];
    const float* bdf = (const float*)d_in[20];
    float* out = (float*)d_out;

    float4* scratch;
    cudaGetSymbolAddress((void**)&scratch, g_rgbd);

    const int wt_coarse = RAYS * 4;           // 16 pts/tile, 4 tiles per coarse ray
    const int wt_fine   = RAYS * 12;          // 12 tiles per fine ray

    mlp_kernel<<<296, BLK>>>(0, wt_coarse, origins, dirs, nearp, farp,
                             w1c, b1c, w2c, b2c, wrc, brc, wdc, bdc, scratch);
    coarse_render<<<RAYS / 8, 256>>>(origins, dirs, nearp, farp, bkgd, out);
    sample_kernel<<<RAYS / 8, 256>>>(nearp, farp);
    mlp_kernel<<<296, BLK>>>(1, wt_fine, origins, dirs, nearp, farp,
                             w1f, b1f, w2f, b2f, wrf, brf, wdf, bdf,
                             scratch + RAYS * NCS);
    fine_render<<<RAYS / 8, 256>>>(origins, dirs, bkgd, out);
}